// round 1
// baseline (speedup 1.0000x reference)
#include <cuda_runtime.h>
#include <cfloat>

#define NN 100000
#define NE 3200000
#define CAP 128

// Scratch (static __device__ globals — allocation-free per harness rules)
__device__ int    g_deg2[2 * NN];   // [0,N): in_deg ; [N,2N): out_deg
__device__ int    g_off[2 * NN];    // exclusive scan of g_deg2 (out half offset by E)
__device__ int    g_cur[2 * NN];    // scatter cursors
__device__ int    g_blk[256];
__device__ int    g_blkoff[256];
__device__ float4 g_csr[2 * NE];    // in-lists [0,E), out-lists [E,2E)
                                    // payload: {deg_val, tot_val, w, ts}

__global__ void k_zero() {
    int i = blockIdx.x * blockDim.x + threadIdx.x;
    if (i < 2 * NN) { g_deg2[i] = 0; g_cur[i] = 0; }
}

__global__ void k_deg(const int* __restrict__ ei, int E) {
    int e = blockIdx.x * blockDim.x + threadIdx.x;
    if (e < E) {
        int src = ei[e], dst = ei[E + e];
        atomicAdd(&g_deg2[dst], 1);        // in-degree
        atomicAdd(&g_deg2[NN + src], 1);   // out-degree
    }
}

__global__ void k_scan1() {
    __shared__ int sh[1024];
    int t = threadIdx.x;
    int i = blockIdx.x * 1024 + t;
    int v = (i < 2 * NN) ? g_deg2[i] : 0;
    sh[t] = v;
    __syncthreads();
    for (int o = 1; o < 1024; o <<= 1) {
        int x = (t >= o) ? sh[t - o] : 0;
        __syncthreads();
        sh[t] += x;
        __syncthreads();
    }
    if (i < 2 * NN) g_off[i] = sh[t] - v;   // exclusive
    if (t == 1023) g_blk[blockIdx.x] = sh[t];
}

__global__ void k_scan2(int nblk) {
    __shared__ int sh[256];
    int t = threadIdx.x;
    int v = (t < nblk) ? g_blk[t] : 0;
    sh[t] = v;
    __syncthreads();
    for (int o = 1; o < 256; o <<= 1) {
        int x = (t >= o) ? sh[t - o] : 0;
        __syncthreads();
        sh[t] += x;
        __syncthreads();
    }
    g_blkoff[t] = sh[t] - v;
}

__global__ void k_scan3() {
    int i = blockIdx.x * 1024 + threadIdx.x;
    if (i < 2 * NN) g_off[i] += g_blkoff[blockIdx.x];
}

__global__ void k_scatter(const int* __restrict__ ei, const float* __restrict__ w,
                          const float* __restrict__ ts, int E) {
    int e = blockIdx.x * blockDim.x + threadIdx.x;
    if (e >= E) return;
    int src = ei[e], dst = ei[E + e];
    float we = w[e], te = ts[e];
    int in_s  = g_deg2[src],      out_s = g_deg2[NN + src];
    int in_d  = g_deg2[dst],      out_d = g_deg2[NN + dst];
    // into dst's in-list: value = in_deg[src], tot_deg[src]
    int p1 = g_off[dst] + atomicAdd(&g_cur[dst], 1);
    g_csr[p1] = make_float4((float)in_s, (float)(in_s + out_s), we, te);
    // into src's out-list: value = out_deg[dst], tot_deg[dst]
    int p2 = g_off[NN + src] + atomicAdd(&g_cur[NN + src], 1);
    g_csr[p2] = make_float4((float)out_d, (float)(in_d + out_d), we, te);
}

__device__ __forceinline__ float wredsum(float v) {
    for (int o = 16; o; o >>= 1) v += __shfl_xor_sync(0xffffffffu, v, o);
    return v;
}
__device__ __forceinline__ float wredmax(float v) {
    for (int o = 16; o; o >>= 1) v = fmaxf(v, __shfl_xor_sync(0xffffffffu, v, o));
    return v;
}
__device__ __forceinline__ float wredmin(float v) {
    for (int o = 16; o; o >>= 1) v = fminf(v, __shfl_xor_sync(0xffffffffu, v, o));
    return v;
}

// One (variant,value) combo: list = A[0..na) ++ B[0..nb)
// Writes 6 floats: sum, mean, max, min, std(unbiased), entropy(base2)
__device__ void combo(const float* __restrict__ A, int na,
                      const float* __restrict__ B, int nb,
                      float* __restrict__ dst, int lane) {
    int m = na + nb;
    float sum = 0.f, mx = -FLT_MAX, mn = FLT_MAX;
    for (int i = lane; i < na; i += 32) { float v = A[i]; sum += v; mx = fmaxf(mx, v); mn = fminf(mn, v); }
    for (int i = lane; i < nb; i += 32) { float v = B[i]; sum += v; mx = fmaxf(mx, v); mn = fminf(mn, v); }
    sum = wredsum(sum); mx = wredmax(mx); mn = wredmin(mn);
    float fm = (float)m;
    float mean = sum / fmaxf(fm, 1.f);
    float sq = 0.f;
    for (int i = lane; i < na; i += 32) { float d = A[i] - mean; sq += d * d; }
    for (int i = lane; i < nb; i += 32) { float d = B[i] - mean; sq += d * d; }
    sq = wredsum(sq);
    float sd = sqrtf(sq / fmaxf(fm - 1.f, 1.f));
    // entropy: sum over elements of log2(count of equal values in segment)
    float slog = 0.f;
    for (int i = lane; i < m; i += 32) {
        float v = (i < na) ? A[i] : B[i - na];
        int c = 0;
        for (int j = 0; j < na; j++) c += (A[j] == v);
        for (int j = 0; j < nb; j++) c += (B[j] == v);
        if (c > 1) slog += __log2f((float)c);
    }
    slog = wredsum(slog);
    float ent = (m > 0) ? (__log2f(fm) - slog / fm) : 0.f;
    if (lane == 0) {
        dst[0] = sum;
        dst[1] = mean;
        dst[2] = (m > 0) ? mx : 0.f;
        dst[3] = (m > 0) ? mn : 0.f;
        dst[4] = sd;
        dst[5] = ent;
    }
}

__global__ void __launch_bounds__(128) k_node(float* __restrict__ out) {
    __shared__ float sh[4][8][CAP];  // [warp][array][idx]
    int warp = threadIdx.x >> 5, lane = threadIdx.x & 31;
    int u = blockIdx.x * 4 + warp;
    if (u >= NN) return;
    int din = g_deg2[u], dout = g_deg2[NN + u];
    int bin = g_off[u], bout = g_off[NN + u];
    int dinc = min(din, CAP), doutc = min(dout, CAP);
    float (*S)[CAP] = sh[warp];
    // arrays: 0=in degval, 1=in totval, 2=in w, 3=in ts, 4..7 out counterparts
    for (int i = lane; i < dinc; i += 32) {
        float4 p = g_csr[bin + i];
        S[0][i] = p.x; S[1][i] = p.y; S[2][i] = p.z; S[3][i] = p.w;
    }
    for (int i = lane; i < doutc; i += 32) {
        float4 p = g_csr[bout + i];
        S[4][i] = p.x; S[5][i] = p.y; S[6][i] = p.z; S[7][i] = p.w;
    }
    __syncwarp();
    float* row = out + (size_t)u * 57;
    if (lane == 0) {
        row[0] = (float)din;
        row[1] = (float)dout;
        row[2] = (float)(din + dout);
    }
    // struct feats: v1 (seg=dst, val=in_deg[src]) / v2 (seg=src, val=out_deg[dst]) / v3 union of tot-deg
    combo(S[0], dinc, nullptr, 0,   row + 3,  lane);
    combo(S[4], doutc, nullptr, 0,  row + 9,  lane);
    combo(S[5], doutc, S[1], dinc,  row + 15, lane);
    // weight feats: v1 in-list w / v2 out-list w / v3 union
    combo(S[2], dinc, nullptr, 0,   row + 21, lane);
    combo(S[6], doutc, nullptr, 0,  row + 27, lane);
    combo(S[6], doutc, S[2], dinc,  row + 33, lane);
    // ts feats
    combo(S[3], dinc, nullptr, 0,   row + 39, lane);
    combo(S[7], doutc, nullptr, 0,  row + 45, lane);
    combo(S[7], doutc, S[3], dinc,  row + 51, lane);
}

extern "C" void kernel_launch(void* const* d_in, const int* in_sizes, int n_in,
                              void* d_out, int out_size) {
    const int*   ei = (const int*)d_in[0];
    const float* w  = (const float*)d_in[1];
    const float* ts = (const float*)d_in[2];
    float* out = (float*)d_out;
    int E = in_sizes[0] / 2;
    if (E > NE) E = NE;

    k_zero<<<(2 * NN + 255) / 256, 256>>>();
    k_deg<<<(E + 255) / 256, 256>>>(ei, E);
    int nblk = (2 * NN + 1023) / 1024;   // 196
    k_scan1<<<nblk, 1024>>>();
    k_scan2<<<1, 256>>>(nblk);
    k_scan3<<<nblk, 1024>>>();
    k_scatter<<<(E + 255) / 256, 256>>>(ei, w, ts, E);
    k_node<<<(NN + 3) / 4, 128>>>(out);
}

// round 2
// speedup vs baseline: 1.3226x; 1.3226x over previous
#include <cuda_runtime.h>
#include <cfloat>

#define NN 100000
#define NE 3200000
#define CAP 128
#define HB  320   // histogram bins for integer-valued (degree) entropy

// Scratch (static __device__ globals — allocation-free per harness rules)
__device__ int    g_deg2[2 * NN];   // [0,N): in_deg ; [N,2N): out_deg
__device__ int    g_off[2 * NN];    // exclusive scan of g_deg2
__device__ int    g_cur[2 * NN];    // scatter cursors
__device__ int    g_blk[256];
__device__ int    g_blkoff[256];
__device__ float4 g_csr[2 * NE];    // in-lists [0,E), out-lists [E,2E)
                                    // payload: {deg_val, tot_val, w, ts}

__global__ void k_zero() {
    int i = blockIdx.x * blockDim.x + threadIdx.x;
    if (i < 2 * NN) { g_deg2[i] = 0; g_cur[i] = 0; }
}

__global__ void k_deg(const int* __restrict__ ei, int E) {
    int e = blockIdx.x * blockDim.x + threadIdx.x;
    if (e < E) {
        int src = ei[e], dst = ei[E + e];
        atomicAdd(&g_deg2[dst], 1);        // in-degree
        atomicAdd(&g_deg2[NN + src], 1);   // out-degree
    }
}

__global__ void k_scan1() {
    __shared__ int sh[1024];
    int t = threadIdx.x;
    int i = blockIdx.x * 1024 + t;
    int v = (i < 2 * NN) ? g_deg2[i] : 0;
    sh[t] = v;
    __syncthreads();
    for (int o = 1; o < 1024; o <<= 1) {
        int x = (t >= o) ? sh[t - o] : 0;
        __syncthreads();
        sh[t] += x;
        __syncthreads();
    }
    if (i < 2 * NN) g_off[i] = sh[t] - v;   // exclusive
    if (t == 1023) g_blk[blockIdx.x] = sh[t];
}

__global__ void k_scan2(int nblk) {
    __shared__ int sh[256];
    int t = threadIdx.x;
    int v = (t < nblk) ? g_blk[t] : 0;
    sh[t] = v;
    __syncthreads();
    for (int o = 1; o < 256; o <<= 1) {
        int x = (t >= o) ? sh[t - o] : 0;
        __syncthreads();
        sh[t] += x;
        __syncthreads();
    }
    g_blkoff[t] = sh[t] - v;
}

__global__ void k_scan3() {
    int i = blockIdx.x * 1024 + threadIdx.x;
    if (i < 2 * NN) g_off[i] += g_blkoff[blockIdx.x];
}

__global__ void k_scatter(const int* __restrict__ ei, const float* __restrict__ w,
                          const float* __restrict__ ts, int E) {
    int e = blockIdx.x * blockDim.x + threadIdx.x;
    if (e >= E) return;
    int src = ei[e], dst = ei[E + e];
    float we = w[e], te = ts[e];
    int in_s  = g_deg2[src],      out_s = g_deg2[NN + src];
    int in_d  = g_deg2[dst],      out_d = g_deg2[NN + dst];
    int p1 = g_off[dst] + atomicAdd(&g_cur[dst], 1);
    g_csr[p1] = make_float4((float)in_s, (float)(in_s + out_s), we, te);
    int p2 = g_off[NN + src] + atomicAdd(&g_cur[NN + src], 1);
    g_csr[p2] = make_float4((float)out_d, (float)(in_d + out_d), we, te);
}

__device__ __forceinline__ float wredsum(float v) {
    for (int o = 16; o; o >>= 1) v += __shfl_xor_sync(0xffffffffu, v, o);
    return v;
}
__device__ __forceinline__ float wredmax(float v) {
    for (int o = 16; o; o >>= 1) v = fmaxf(v, __shfl_xor_sync(0xffffffffu, v, o));
    return v;
}
__device__ __forceinline__ float wredmin(float v) {
    for (int o = 16; o; o >>= 1) v = fminf(v, __shfl_xor_sync(0xffffffffu, v, o));
    return v;
}

// Entropy of integer-valued list (values in [0,HB)) via shared histogram.
// hist must be all-zero on entry and is left all-zero on exit.
__device__ __forceinline__ float ent_hist(const float* __restrict__ A, int na,
                                          const float* __restrict__ B, int nb,
                                          int* __restrict__ hist,
                                          const float* __restrict__ lut, int lane) {
    int m = na + nb;
    if (m == 0) return 0.f;
    for (int i = lane; i < m; i += 32) {
        int v = min((int)((i < na) ? A[i] : B[i - na]), HB - 1);
        atomicAdd(&hist[v], 1);
    }
    __syncwarp();
    float slog = 0.f;
    for (int i = lane; i < m; i += 32) {
        int v = min((int)((i < na) ? A[i] : B[i - na]), HB - 1);
        slog += lut[hist[v]];
    }
    slog = wredsum(slog);
    __syncwarp();
    for (int i = lane; i < m; i += 32) {
        int v = min((int)((i < na) ? A[i] : B[i - na]), HB - 1);
        hist[v] = 0;
    }
    __syncwarp();
    float fm = (float)m;
    return __log2f(fm) - slog / fm;
}

// Entropy of float list via O(m^2) pairwise equality counting.
__device__ __forceinline__ float ent_pair(const float* __restrict__ A, int na,
                                          const float* __restrict__ B, int nb,
                                          const float* __restrict__ lut, int lane) {
    int m = na + nb;
    if (m == 0) return 0.f;
    float slog = 0.f;
    for (int i = lane; i < m; i += 32) {
        float v = (i < na) ? A[i] : B[i - na];
        int c = 0;
        #pragma unroll 4
        for (int j = 0; j < na; j++) c += (A[j] == v);
        #pragma unroll 4
        for (int j = 0; j < nb; j++) c += (B[j] == v);
        slog += lut[c];   // lut[1] == 0
    }
    slog = wredsum(slog);
    float fm = (float)m;
    return __log2f(fm) - slog / fm;
}

// Emit {sum, mean, max, min, std(unbiased, closed-form), ent} — lane 0 only.
__device__ __forceinline__ void emit(float* __restrict__ dst, float s, float q,
                                     float mx, float mn, int m, float ent, int lane) {
    if (lane != 0) return;
    float fm = (float)m;
    float mean = s / fmaxf(fm, 1.f);
    float sq = fmaxf(q - s * mean, 0.f);
    float sd = (m > 1) ? sqrtf(sq / (fm - 1.f)) : 0.f;
    dst[0] = s;
    dst[1] = mean;
    dst[2] = (m > 0) ? mx : 0.f;
    dst[3] = (m > 0) ? mn : 0.f;
    dst[4] = sd;
    dst[5] = ent;
}

__global__ void __launch_bounds__(128) k_node(float* __restrict__ out) {
    __shared__ float sh[4][8][CAP];       // [warp][array][idx]
    __shared__ int   hist[4][HB];         // per-warp integer histogram
    __shared__ float lut[2 * CAP + 1];    // lut[c] = log2(c), lut[0]=lut[1]=0

    int warp = threadIdx.x >> 5, lane = threadIdx.x & 31;
    for (int i = threadIdx.x; i <= 2 * CAP; i += blockDim.x)
        lut[i] = (i > 1) ? __log2f((float)i) : 0.f;
    for (int i = lane; i < HB; i += 32) hist[warp][i] = 0;
    __syncthreads();

    int u = blockIdx.x * 4 + warp;
    if (u >= NN) return;

    int din = g_deg2[u], dout = g_deg2[NN + u];
    int bin = g_off[u], bout = g_off[NN + u];
    int dinc = min(din, CAP), doutc = min(dout, CAP);
    float (*S)[CAP] = sh[warp];
    int* H = hist[warp];

    // per-lane partials: [dir][type] type: 0=degval 1=totval 2=w 3=ts
    float is[4], iq[4], imx[4], imn[4], os[4], oq[4], omx[4], omn[4];
    #pragma unroll
    for (int t = 0; t < 4; t++) {
        is[t] = oq[t] = iq[t] = os[t] = 0.f;
        imx[t] = omx[t] = -FLT_MAX;
        imn[t] = omn[t] = FLT_MAX;
    }
    for (int i = lane; i < dinc; i += 32) {
        float4 p = g_csr[bin + i];
        float v[4] = {p.x, p.y, p.z, p.w};
        S[0][i] = p.x; S[1][i] = p.y; S[2][i] = p.z; S[3][i] = p.w;
        #pragma unroll
        for (int t = 0; t < 4; t++) {
            is[t] += v[t]; iq[t] += v[t] * v[t];
            imx[t] = fmaxf(imx[t], v[t]); imn[t] = fminf(imn[t], v[t]);
        }
    }
    for (int i = lane; i < doutc; i += 32) {
        float4 p = g_csr[bout + i];
        float v[4] = {p.x, p.y, p.z, p.w};
        S[4][i] = p.x; S[5][i] = p.y; S[6][i] = p.z; S[7][i] = p.w;
        #pragma unroll
        for (int t = 0; t < 4; t++) {
            os[t] += v[t]; oq[t] += v[t] * v[t];
            omx[t] = fmaxf(omx[t], v[t]); omn[t] = fminf(omn[t], v[t]);
        }
    }
    __syncwarp();
    #pragma unroll
    for (int t = 0; t < 4; t++) {
        is[t] = wredsum(is[t]);  iq[t] = wredsum(iq[t]);
        imx[t] = wredmax(imx[t]); imn[t] = wredmin(imn[t]);
        os[t] = wredsum(os[t]);  oq[t] = wredsum(oq[t]);
        omx[t] = wredmax(omx[t]); omn[t] = wredmin(omn[t]);
    }

    float* row = out + (size_t)u * 57;
    if (lane == 0) {
        row[0] = (float)din;
        row[1] = (float)dout;
        row[2] = (float)(din + dout);
    }
    int mu = dinc + doutc;
    float e;

    // struct feats
    e = ent_hist(S[0], dinc, nullptr, 0, H, lut, lane);
    emit(row + 3, is[0], iq[0], imx[0], imn[0], dinc, e, lane);
    e = ent_hist(S[4], doutc, nullptr, 0, H, lut, lane);
    emit(row + 9, os[0], oq[0], omx[0], omn[0], doutc, e, lane);
    e = ent_hist(S[5], doutc, S[1], dinc, H, lut, lane);
    emit(row + 15, is[1] + os[1], iq[1] + oq[1], fmaxf(imx[1], omx[1]),
         fminf(imn[1], omn[1]), mu, e, lane);

    // weight feats
    e = ent_pair(S[2], dinc, nullptr, 0, lut, lane);
    emit(row + 21, is[2], iq[2], imx[2], imn[2], dinc, e, lane);
    e = ent_pair(S[6], doutc, nullptr, 0, lut, lane);
    emit(row + 27, os[2], oq[2], omx[2], omn[2], doutc, e, lane);
    e = ent_pair(S[6], doutc, S[2], dinc, lut, lane);
    emit(row + 33, is[2] + os[2], iq[2] + oq[2], fmaxf(imx[2], omx[2]),
         fminf(imn[2], omn[2]), mu, e, lane);

    // ts feats
    e = ent_pair(S[3], dinc, nullptr, 0, lut, lane);
    emit(row + 39, is[3], iq[3], imx[3], imn[3], dinc, e, lane);
    e = ent_pair(S[7], doutc, nullptr, 0, lut, lane);
    emit(row + 45, os[3], oq[3], omx[3], omn[3], doutc, e, lane);
    e = ent_pair(S[7], doutc, S[3], dinc, lut, lane);
    emit(row + 51, is[3] + os[3], iq[3] + oq[3], fmaxf(imx[3], omx[3]),
         fminf(imn[3], omn[3]), mu, e, lane);
}

extern "C" void kernel_launch(void* const* d_in, const int* in_sizes, int n_in,
                              void* d_out, int out_size) {
    const int*   ei = (const int*)d_in[0];
    const float* w  = (const float*)d_in[1];
    const float* ts = (const float*)d_in[2];
    float* out = (float*)d_out;
    int E = in_sizes[0] / 2;
    if (E > NE) E = NE;

    k_zero<<<(2 * NN + 255) / 256, 256>>>();
    k_deg<<<(E + 255) / 256, 256>>>(ei, E);
    int nblk = (2 * NN + 1023) / 1024;   // 196
    k_scan1<<<nblk, 1024>>>();
    k_scan2<<<1, 256>>>(nblk);
    k_scan3<<<nblk, 1024>>>();
    k_scatter<<<(E + 255) / 256, 256>>>(ei, w, ts, E);
    k_node<<<(NN + 3) / 4, 128>>>(out);
}

// round 3
// speedup vs baseline: 1.5658x; 1.1839x over previous
#include <cuda_runtime.h>
#include <cfloat>

#define NN 100000
#define NE 3200000
#define CAP 128
#define HB  320          // histogram bins for integer-valued (degree) entropy
#define BMW 512          // bitmap words per warp (512*32 = 16384 buckets)

// Scratch (static __device__ globals — allocation-free per harness rules)
__device__ int    g_deg2[2 * NN];   // [0,N): in_deg ; [N,2N): out_deg
__device__ int    g_off[2 * NN];    // exclusive scan of g_deg2
__device__ int    g_cur[2 * NN];    // scatter cursors
__device__ int    g_blk[256];
__device__ int    g_blkoff[256];
__device__ float4 g_csr[2 * NE];    // in-lists [0,E), out-lists [E,2E)
                                    // payload: {deg_val, tot_val, w, ts}

__global__ void k_zero() {
    int i = blockIdx.x * blockDim.x + threadIdx.x;
    if (i < 2 * NN) { g_deg2[i] = 0; g_cur[i] = 0; }
}

__global__ void k_deg(const int* __restrict__ ei, int E) {
    int e = blockIdx.x * blockDim.x + threadIdx.x;
    if (e < E) {
        int src = ei[e], dst = ei[E + e];
        atomicAdd(&g_deg2[dst], 1);        // in-degree
        atomicAdd(&g_deg2[NN + src], 1);   // out-degree
    }
}

__global__ void k_scan1() {
    __shared__ int sh[1024];
    int t = threadIdx.x;
    int i = blockIdx.x * 1024 + t;
    int v = (i < 2 * NN) ? g_deg2[i] : 0;
    sh[t] = v;
    __syncthreads();
    for (int o = 1; o < 1024; o <<= 1) {
        int x = (t >= o) ? sh[t - o] : 0;
        __syncthreads();
        sh[t] += x;
        __syncthreads();
    }
    if (i < 2 * NN) g_off[i] = sh[t] - v;   // exclusive
    if (t == 1023) g_blk[blockIdx.x] = sh[t];
}

__global__ void k_scan2(int nblk) {
    __shared__ int sh[256];
    int t = threadIdx.x;
    int v = (t < nblk) ? g_blk[t] : 0;
    sh[t] = v;
    __syncthreads();
    for (int o = 1; o < 256; o <<= 1) {
        int x = (t >= o) ? sh[t - o] : 0;
        __syncthreads();
        sh[t] += x;
        __syncthreads();
    }
    g_blkoff[t] = sh[t] - v;
}

__global__ void k_scan3() {
    int i = blockIdx.x * 1024 + threadIdx.x;
    if (i < 2 * NN) g_off[i] += g_blkoff[blockIdx.x];
}

__global__ void k_scatter(const int* __restrict__ ei, const float* __restrict__ w,
                          const float* __restrict__ ts, int E) {
    int e = blockIdx.x * blockDim.x + threadIdx.x;
    if (e >= E) return;
    int src = ei[e], dst = ei[E + e];
    float we = w[e], te = ts[e];
    int in_s  = g_deg2[src],      out_s = g_deg2[NN + src];
    int in_d  = g_deg2[dst],      out_d = g_deg2[NN + dst];
    int p1 = g_off[dst] + atomicAdd(&g_cur[dst], 1);
    g_csr[p1] = make_float4((float)in_s, (float)(in_s + out_s), we, te);
    int p2 = g_off[NN + src] + atomicAdd(&g_cur[NN + src], 1);
    g_csr[p2] = make_float4((float)out_d, (float)(in_d + out_d), we, te);
}

__device__ __forceinline__ float wredsum(float v) {
    for (int o = 16; o; o >>= 1) v += __shfl_xor_sync(0xffffffffu, v, o);
    return v;
}
__device__ __forceinline__ float wredmax(float v) {
    for (int o = 16; o; o >>= 1) v = fmaxf(v, __shfl_xor_sync(0xffffffffu, v, o));
    return v;
}
__device__ __forceinline__ float wredmin(float v) {
    for (int o = 16; o; o >>= 1) v = fminf(v, __shfl_xor_sync(0xffffffffu, v, o));
    return v;
}

// Entropy of integer-valued list (values in [0,HB)) via shared histogram.
// hist must be all-zero on entry and is left all-zero on exit.
__device__ __forceinline__ float ent_hist(const float* __restrict__ A, int na,
                                          const float* __restrict__ B, int nb,
                                          int* __restrict__ hist,
                                          const float* __restrict__ lut, int lane) {
    int m = na + nb;
    if (m == 0) return 0.f;
    for (int i = lane; i < m; i += 32) {
        int v = min((int)((i < na) ? A[i] : B[i - na]), HB - 1);
        atomicAdd(&hist[v], 1);
    }
    __syncwarp();
    float slog = 0.f;
    for (int i = lane; i < m; i += 32) {
        int v = min((int)((i < na) ? A[i] : B[i - na]), HB - 1);
        slog += lut[hist[v]];
    }
    slog = wredsum(slog);
    __syncwarp();
    for (int i = lane; i < m; i += 32) {
        int v = min((int)((i < na) ? A[i] : B[i - na]), HB - 1);
        hist[v] = 0;
    }
    __syncwarp();
    float fm = (float)m;
    return __log2f(fm) - slog / fm;
}

// Exact O(m^2) pairwise entropy (fallback path).
__device__ __noinline__ float ent_pair(const float* __restrict__ A, int na,
                                       const float* __restrict__ B, int nb,
                                       const float* __restrict__ lut, int lane) {
    int m = na + nb;
    float slog = 0.f;
    for (int i = lane; i < m; i += 32) {
        float v = (i < na) ? A[i] : B[i - na];
        int c = 0;
        #pragma unroll 4
        for (int j = 0; j < na; j++) c += (A[j] == v);
        #pragma unroll 4
        for (int j = 0; j < nb; j++) c += (B[j] == v);
        slog += lut[c];   // lut[1] == 0
    }
    slog = wredsum(slog);
    float fm = (float)m;
    return __log2f(fm) - slog / fm;
}

// Exact float entropy with hash-bitmap all-unique fast path.
// bm: per-warp 512-word shared bitmap, all-zero on entry, left all-zero.
// Any true duplicate is guaranteed to trigger the fallback (atomicOr is atomic);
// hash collisions between distinct values merely cause a spurious (still exact)
// fallback.
__device__ __forceinline__ float ent_float(const float* __restrict__ A, int na,
                                           const float* __restrict__ B, int nb,
                                           unsigned* __restrict__ bm,
                                           const float* __restrict__ lut, int lane) {
    int m = na + nb;
    if (m == 0) return 0.f;
    bool col = false;
    for (int i = lane; i < m; i += 32) {
        float v = (i < na) ? A[i] : B[i - na];
        unsigned h = (__float_as_uint(v) * 2654435761u) >> 18;  // 14-bit bucket
        unsigned old = atomicOr(&bm[h >> 5], 1u << (h & 31));
        col |= (old >> (h & 31)) & 1u;
    }
    bool any = __any_sync(0xffffffffu, col);
    __syncwarp();
    for (int i = lane; i < m; i += 32) {     // clear only touched words
        float v = (i < na) ? A[i] : B[i - na];
        unsigned h = (__float_as_uint(v) * 2654435761u) >> 18;
        bm[h >> 5] = 0u;
    }
    __syncwarp();
    if (!any) return __log2f((float)m);      // all unique: ent = log2(m) exactly
    return ent_pair(A, na, B, nb, lut, lane);
}

// Emit {sum, mean, max, min, std(unbiased, closed-form), ent} — lane 0 only.
__device__ __forceinline__ void emit(float* __restrict__ dst, float s, float q,
                                     float mx, float mn, int m, float ent, int lane) {
    if (lane != 0) return;
    float fm = (float)m;
    float mean = s / fmaxf(fm, 1.f);
    float sq = fmaxf(q - s * mean, 0.f);
    float sd = (m > 1) ? sqrtf(sq / (fm - 1.f)) : 0.f;
    dst[0] = s;
    dst[1] = mean;
    dst[2] = (m > 0) ? mx : 0.f;
    dst[3] = (m > 0) ? mn : 0.f;
    dst[4] = sd;
    dst[5] = ent;
}

__global__ void __launch_bounds__(128) k_node(float* __restrict__ out) {
    __shared__ float    sh[4][8][CAP];       // [warp][array][idx]
    __shared__ int      hist[4][HB];         // per-warp integer histogram
    __shared__ unsigned bmap[4][BMW];        // per-warp hash bitmap (16K buckets)
    __shared__ float    lut[2 * CAP + 1];    // lut[c] = log2(c), lut[0]=lut[1]=0

    int warp = threadIdx.x >> 5, lane = threadIdx.x & 31;
    for (int i = threadIdx.x; i <= 2 * CAP; i += blockDim.x)
        lut[i] = (i > 1) ? __log2f((float)i) : 0.f;
    for (int i = lane; i < HB; i += 32) hist[warp][i] = 0;
    for (int i = lane; i < BMW; i += 32) bmap[warp][i] = 0u;
    __syncthreads();

    int u = blockIdx.x * 4 + warp;
    if (u >= NN) return;

    int din = g_deg2[u], dout = g_deg2[NN + u];
    int bin = g_off[u], bout = g_off[NN + u];
    int dinc = min(din, CAP), doutc = min(dout, CAP);
    float (*S)[CAP] = sh[warp];
    int* H = hist[warp];
    unsigned* BM = bmap[warp];

    // per-lane partials: [dir][type] type: 0=degval 1=totval 2=w 3=ts
    float is[4], iq[4], imx[4], imn[4], os[4], oq[4], omx[4], omn[4];
    #pragma unroll
    for (int t = 0; t < 4; t++) {
        is[t] = oq[t] = iq[t] = os[t] = 0.f;
        imx[t] = omx[t] = -FLT_MAX;
        imn[t] = omn[t] = FLT_MAX;
    }
    for (int i = lane; i < dinc; i += 32) {
        float4 p = g_csr[bin + i];
        float v[4] = {p.x, p.y, p.z, p.w};
        S[0][i] = p.x; S[1][i] = p.y; S[2][i] = p.z; S[3][i] = p.w;
        #pragma unroll
        for (int t = 0; t < 4; t++) {
            is[t] += v[t]; iq[t] += v[t] * v[t];
            imx[t] = fmaxf(imx[t], v[t]); imn[t] = fminf(imn[t], v[t]);
        }
    }
    for (int i = lane; i < doutc; i += 32) {
        float4 p = g_csr[bout + i];
        float v[4] = {p.x, p.y, p.z, p.w};
        S[4][i] = p.x; S[5][i] = p.y; S[6][i] = p.z; S[7][i] = p.w;
        #pragma unroll
        for (int t = 0; t < 4; t++) {
            os[t] += v[t]; oq[t] += v[t] * v[t];
            omx[t] = fmaxf(omx[t], v[t]); omn[t] = fminf(omn[t], v[t]);
        }
    }
    __syncwarp();
    #pragma unroll
    for (int t = 0; t < 4; t++) {
        is[t] = wredsum(is[t]);  iq[t] = wredsum(iq[t]);
        imx[t] = wredmax(imx[t]); imn[t] = wredmin(imn[t]);
        os[t] = wredsum(os[t]);  oq[t] = wredsum(oq[t]);
        omx[t] = wredmax(omx[t]); omn[t] = wredmin(omn[t]);
    }

    float* row = out + (size_t)u * 57;
    if (lane == 0) {
        row[0] = (float)din;
        row[1] = (float)dout;
        row[2] = (float)(din + dout);
    }
    int mu = dinc + doutc;
    float e;

    // struct feats (integer-valued: histogram entropy)
    e = ent_hist(S[0], dinc, nullptr, 0, H, lut, lane);
    emit(row + 3, is[0], iq[0], imx[0], imn[0], dinc, e, lane);
    e = ent_hist(S[4], doutc, nullptr, 0, H, lut, lane);
    emit(row + 9, os[0], oq[0], omx[0], omn[0], doutc, e, lane);
    e = ent_hist(S[5], doutc, S[1], dinc, H, lut, lane);
    emit(row + 15, is[1] + os[1], iq[1] + oq[1], fmaxf(imx[1], omx[1]),
         fminf(imn[1], omn[1]), mu, e, lane);

    // weight feats (float: bitmap fast path + exact fallback)
    e = ent_float(S[2], dinc, nullptr, 0, BM, lut, lane);
    emit(row + 21, is[2], iq[2], imx[2], imn[2], dinc, e, lane);
    e = ent_float(S[6], doutc, nullptr, 0, BM, lut, lane);
    emit(row + 27, os[2], oq[2], omx[2], omn[2], doutc, e, lane);
    e = ent_float(S[6], doutc, S[2], dinc, BM, lut, lane);
    emit(row + 33, is[2] + os[2], iq[2] + oq[2], fmaxf(imx[2], omx[2]),
         fminf(imn[2], omn[2]), mu, e, lane);

    // ts feats
    e = ent_float(S[3], dinc, nullptr, 0, BM, lut, lane);
    emit(row + 39, is[3], iq[3], imx[3], imn[3], dinc, e, lane);
    e = ent_float(S[7], doutc, nullptr, 0, BM, lut, lane);
    emit(row + 45, os[3], oq[3], omx[3], omn[3], doutc, e, lane);
    e = ent_float(S[7], doutc, S[3], dinc, BM, lut, lane);
    emit(row + 51, is[3] + os[3], iq[3] + oq[3], fmaxf(imx[3], omx[3]),
         fminf(imn[3], omn[3]), mu, e, lane);
}

extern "C" void kernel_launch(void* const* d_in, const int* in_sizes, int n_in,
                              void* d_out, int out_size) {
    const int*   ei = (const int*)d_in[0];
    const float* w  = (const float*)d_in[1];
    const float* ts = (const float*)d_in[2];
    float* out = (float*)d_out;
    int E = in_sizes[0] / 2;
    if (E > NE) E = NE;

    k_zero<<<(2 * NN + 255) / 256, 256>>>();
    k_deg<<<(E + 255) / 256, 256>>>(ei, E);
    int nblk = (2 * NN + 1023) / 1024;   // 196
    k_scan1<<<nblk, 1024>>>();
    k_scan2<<<1, 256>>>(nblk);
    k_scan3<<<nblk, 1024>>>();
    k_scatter<<<(E + 255) / 256, 256>>>(ei, w, ts, E);
    k_node<<<(NN + 3) / 4, 128>>>(out);
}